// round 1
// baseline (speedup 1.0000x reference)
#include <cuda_runtime.h>
#include <math.h>

#define B_TOK   4096
#define DM      1024
#define DH      2048
#define N_TILES 8

#define BM 128
#define BN 64
#define BK 16
#define TM 8
#define TN 4

// -------- scratch (device globals; no allocation allowed) --------
__device__ float g_Hr [B_TOK * DM];   // router hidden (gelu(x@Wr1+br1))
__device__ float g_H2 [B_TOK * DH];   // tile hidden, compact per-tile order
__device__ float g_sel[B_TOK * DM];   // selected tile output, token order
__device__ int   g_tile[B_TOK];
__device__ int   g_perm[B_TOK];       // compact order -> token id
__device__ int   g_cnt[N_TILES];
__device__ int   g_off[N_TILES];
__device__ int   g_cur[N_TILES];

__device__ __forceinline__ float gelu_exact(float v) {
    return 0.5f * v * (1.0f + erff(v * 0.70710678118654752440f));
}

__global__ void zero_kernel() {
    int i = threadIdx.x;
    if (i < N_TILES) { g_cnt[i] = 0; g_cur[i] = 0; }
}

// ----------------------------------------------------------------------------
// Generic fp32 tiled GEMM: C = act(A @ W + bias)
//   MODE 0: plain.  A row m, C row m.                       (M = M0 fixed)
//   MODE 1: gather. A row = x[perm[off+m]], C row = off+m.  (M = cnt[tile])
//   MODE 2: compact->scatter. A row = off+m, C row = perm[off+m].
// W is row-major (K x N), per-tile stride K*N; bias per-tile stride N.
// ----------------------------------------------------------------------------
template<int MODE, bool ACT>
__global__ __launch_bounds__(256) void gemm_k(
    const float* __restrict__ A,
    const float* __restrict__ Wg,
    const float* __restrict__ bg,
    float* __restrict__ C,
    int N, int K, int M0)
{
    const int tile = (MODE == 0) ? 0 : blockIdx.z;
    const float* W    = Wg + (size_t)tile * (size_t)K * (size_t)N;
    const float* bias = bg + (size_t)tile * (size_t)N;

    int Mvalid, moff;
    if (MODE == 0) { Mvalid = M0;          moff = 0; }
    else           { Mvalid = g_cnt[tile]; moff = g_off[tile]; }

    const int mstart = blockIdx.y * BM;
    if (mstart >= Mvalid) return;
    const int nstart = blockIdx.x * BN;

    __shared__ float As[BK][BM + 4];
    __shared__ float Ws[BK][BN];

    const int tid = threadIdx.x;
    const int tx  = tid & 15;     // 0..15 -> N direction (4 cols each)
    const int ty  = tid >> 4;     // 0..15 -> M direction (8 rows each)

    // A loader assignment: row ra (0..127), half-row kg (0 or 8)
    const int ra = tid >> 1;
    const int kg = (tid & 1) * 8;
    const float* Arow;
    {
        int mg = mstart + ra;
        if (mg >= Mvalid) mg = Mvalid - 1;   // clamp (Mvalid >= 1 here)
        if (MODE == 0)       Arow = A + (size_t)mg * K;
        else if (MODE == 1)  Arow = A + (size_t)g_perm[moff + mg] * K;
        else                 Arow = A + (size_t)(moff + mg) * K;
    }

    float acc[TM][TN];
#pragma unroll
    for (int i = 0; i < TM; i++)
#pragma unroll
        for (int j = 0; j < TN; j++) acc[i][j] = 0.f;

    const int wk = tid >> 4;          // 0..15 : k within tile
    const int wn = (tid & 15) << 2;   // 0..60 : 4-col group

    for (int k0 = 0; k0 < K; k0 += BK) {
        float4 a0 = *(const float4*)(Arow + k0 + kg);
        float4 a1 = *(const float4*)(Arow + k0 + kg + 4);
        As[kg + 0][ra] = a0.x; As[kg + 1][ra] = a0.y;
        As[kg + 2][ra] = a0.z; As[kg + 3][ra] = a0.w;
        As[kg + 4][ra] = a1.x; As[kg + 5][ra] = a1.y;
        As[kg + 6][ra] = a1.z; As[kg + 7][ra] = a1.w;

        float4 wv = *(const float4*)(W + (size_t)(k0 + wk) * N + nstart + wn);
        *(float4*)&Ws[wk][wn] = wv;

        __syncthreads();
#pragma unroll
        for (int kk = 0; kk < BK; kk++) {
            float a[TM], b[TN];
#pragma unroll
            for (int i = 0; i < TM; i++) a[i] = As[kk][ty * TM + i];
#pragma unroll
            for (int j = 0; j < TN; j++) b[j] = Ws[kk][tx * TN + j];
#pragma unroll
            for (int i = 0; i < TM; i++)
#pragma unroll
                for (int j = 0; j < TN; j++)
                    acc[i][j] = fmaf(a[i], b[j], acc[i][j]);
        }
        __syncthreads();
    }

    const int cn = nstart + tx * TN;
    float4 bv = *(const float4*)(bias + cn);
#pragma unroll
    for (int i = 0; i < TM; i++) {
        int mg = mstart + ty * TM + i;
        if (mg < Mvalid) {
            float* crow;
            if (MODE == 0)      crow = C + (size_t)mg * N;
            else if (MODE == 1) crow = C + (size_t)(moff + mg) * N;
            else                crow = C + (size_t)g_perm[moff + mg] * N;
            float4 v;
            v.x = acc[i][0] + bv.x; v.y = acc[i][1] + bv.y;
            v.z = acc[i][2] + bv.z; v.w = acc[i][3] + bv.w;
            if (ACT) {
                v.x = gelu_exact(v.x); v.y = gelu_exact(v.y);
                v.z = gelu_exact(v.z); v.w = gelu_exact(v.w);
            }
            *(float4*)(crow + cn) = v;
        }
    }
}

// ----------------------------------------------------------------------------
// Router logits + argmax: one warp per token. logits = (Hr @ Wr2 + br2) / 0.5
// ----------------------------------------------------------------------------
__global__ __launch_bounds__(256) void router_argmax_kernel(
    const float* __restrict__ Hr, const float* __restrict__ Wr2,
    const float* __restrict__ br2,
    float* __restrict__ out_logits, float* __restrict__ out_idx)
{
    const int token = blockIdx.x * 8 + (threadIdx.x >> 5);
    const int lane  = threadIdx.x & 31;
    const float* h  = Hr + (size_t)token * DM;

    float acc[N_TILES];
#pragma unroll
    for (int n = 0; n < N_TILES; n++) acc[n] = 0.f;

    for (int k = lane; k < DM; k += 32) {
        float hv = h[k];
        float4 w0 = *(const float4*)(Wr2 + (size_t)k * N_TILES);
        float4 w1 = *(const float4*)(Wr2 + (size_t)k * N_TILES + 4);
        acc[0] = fmaf(hv, w0.x, acc[0]); acc[1] = fmaf(hv, w0.y, acc[1]);
        acc[2] = fmaf(hv, w0.z, acc[2]); acc[3] = fmaf(hv, w0.w, acc[3]);
        acc[4] = fmaf(hv, w1.x, acc[4]); acc[5] = fmaf(hv, w1.y, acc[5]);
        acc[6] = fmaf(hv, w1.z, acc[6]); acc[7] = fmaf(hv, w1.w, acc[7]);
    }
#pragma unroll
    for (int n = 0; n < N_TILES; n++) {
#pragma unroll
        for (int s = 16; s > 0; s >>= 1)
            acc[n] += __shfl_xor_sync(0xFFFFFFFFu, acc[n], s);
    }
    if (lane == 0) {
        float best = -1e30f; int bi = 0;
#pragma unroll
        for (int n = 0; n < N_TILES; n++) {
            float l = (acc[n] + br2[n]) * 2.0f;   // / TEMPERATURE (0.5)
            if (out_logits) out_logits[(size_t)token * N_TILES + n] = l;
            if (l > best) { best = l; bi = n; }   // first-max tie break, like argmax
        }
        g_tile[token] = bi;
        atomicAdd(&g_cnt[bi], 1);
        if (out_idx) out_idx[token] = (float)bi;
    }
}

__global__ void offsets_kernel() {
    if (threadIdx.x == 0) {
        int s = 0;
        for (int t = 0; t < N_TILES; t++) { g_off[t] = s; s += g_cnt[t]; }
    }
}

__global__ void scatter_kernel() {
    int i = blockIdx.x * blockDim.x + threadIdx.x;
    if (i < B_TOK) {
        int t = g_tile[i];
        int pos = g_off[t] + atomicAdd(&g_cur[t], 1);
        g_perm[pos] = i;
    }
}

// ----------------------------------------------------------------------------
extern "C" void kernel_launch(void* const* d_in, const int* in_sizes, int n_in,
                              void* d_out, int out_size)
{
    const float* x   = (const float*)d_in[0];
    const float* Wr1 = (const float*)d_in[1];
    const float* br1 = (const float*)d_in[2];
    const float* Wr2 = (const float*)d_in[3];
    const float* br2 = (const float*)d_in[4];
    const float* W1  = (const float*)d_in[5];
    const float* b1  = (const float*)d_in[6];
    const float* W2  = (const float*)d_in[7];
    const float* b2  = (const float*)d_in[8];
    const float* Wo  = (const float*)d_in[9];
    const float* bo  = (const float*)d_in[10];

    float* out = (float*)d_out;
    float* out_main   = out;                 // (B, D) output
    float* out_idx    = nullptr;             // (B,) tile_idx as f32
    float* out_logits = nullptr;             // (B, T) route_logits
    const long long need_all = (long long)B_TOK * DM + B_TOK + (long long)B_TOK * N_TILES;
    if ((long long)out_size >= need_all) {
        out_idx    = out + (size_t)B_TOK * DM;
        out_logits = out + (size_t)B_TOK * DM + B_TOK;
    } else if ((long long)out_size >= (long long)B_TOK * DM + B_TOK) {
        out_idx = out + (size_t)B_TOK * DM;
    }

    // 1) reset per-run counters (graph replays must be deterministic)
    zero_kernel<<<1, 32>>>();

    // 2) router hidden: Hr = gelu(x @ Wr1 + br1)           (4096x1024x1024)
    gemm_k<0, true><<<dim3(DM / BN, B_TOK / BM), 256>>>(
        x, Wr1, br1, g_Hr, DM, DM, B_TOK);

    // 3) logits + argmax + per-tile counts
    router_argmax_kernel<<<B_TOK / 8, 256>>>(g_Hr, Wr2, br2, out_logits, out_idx);

    // 4) offsets + scatter token ids into compact per-tile lists
    offsets_kernel<<<1, 1>>>();
    scatter_kernel<<<B_TOK / 256, 256>>>();

    // 5) dispatched tile MLP layer 1: H2 = gelu(x[perm] @ W1[t] + b1[t])
    gemm_k<1, true><<<dim3(DH / BN, B_TOK / BM, N_TILES), 256>>>(
        x, W1, b1, g_H2, DH, DM, 0);

    // 6) dispatched tile MLP layer 2: sel[token] = H2 @ W2[t] + b2[t]
    gemm_k<2, false><<<dim3(DM / BN, B_TOK / BM, N_TILES), 256>>>(
        g_H2, W2, b2, g_sel, DM, DH, 0);

    // 7) output projection: out = sel @ Wo + bo
    gemm_k<0, false><<<dim3(DM / BN, B_TOK / BM), 256>>>(
        g_sel, Wo, bo, out_main, DM, DM, B_TOK);
}

// round 6
// speedup vs baseline: 7.8013x; 7.8013x over previous
#include <cuda_runtime.h>
#include <cuda_bf16.h>
#include <math.h>
#include <stdint.h>

#define B_TOK   4096
#define DM      1024
#define DH      2048
#define N_TILES 8

typedef __nv_bfloat16 bf16;

// ---------------- scratch (device globals; no allocation allowed) -----------
__device__ bf16  g_xhi [B_TOK * DM];
__device__ bf16  g_xlo [B_TOK * DM];
__device__ float g_Hr  [B_TOK * DM];
__device__ bf16  g_H2hi[B_TOK * DH];
__device__ bf16  g_H2lo[B_TOK * DH];
__device__ bf16  g_selhi[B_TOK * DM];
__device__ bf16  g_sello[B_TOK * DM];
// transposed weights [tiles][N][K] (K contiguous)
__device__ bf16  g_Wr1hi[DM * DM],            g_Wr1lo[DM * DM];
__device__ bf16  g_W1hi [N_TILES * DM * DH],  g_W1lo [N_TILES * DM * DH];
__device__ bf16  g_W2hi [N_TILES * DH * DM],  g_W2lo [N_TILES * DH * DM];
__device__ bf16  g_Wohi [DM * DM],            g_Wolo [DM * DM];
__device__ int   g_tile[B_TOK];
__device__ int   g_perm[B_TOK];
__device__ int   g_cnt[N_TILES];
__device__ int   g_off[N_TILES];
__device__ int   g_cur[N_TILES];

// ---------------- helpers ----------------------------------------------------
__device__ __forceinline__ void mma16816(float* c, const uint32_t* a, const uint32_t* b) {
    asm volatile("mma.sync.aligned.m16n8k16.row.col.f32.bf16.bf16.f32 "
                 "{%0,%1,%2,%3}, {%4,%5,%6,%7}, {%8,%9}, {%0,%1,%2,%3};"
                 : "+f"(c[0]), "+f"(c[1]), "+f"(c[2]), "+f"(c[3])
                 : "r"(a[0]), "r"(a[1]), "r"(a[2]), "r"(a[3]),
                   "r"(b[0]), "r"(b[1]));
}

__device__ __forceinline__ float gelu_exact(float v) {
    return 0.5f * v * (1.0f + erff(v * 0.70710678118654752440f));
}

// ---------------- small kernels ---------------------------------------------
__global__ void zero_kernel() {
    int i = threadIdx.x;
    if (i < N_TILES) { g_cnt[i] = 0; g_cur[i] = 0; }
}

__global__ void split_acts_kernel(const float* __restrict__ src,
                                  bf16* __restrict__ xhi, bf16* __restrict__ xlo) {
    int i = blockIdx.x * blockDim.x + threadIdx.x;   // float4 index
    const float4 v = ((const float4*)src)[i];
    float f[4] = {v.x, v.y, v.z, v.w};
    bf16 h[4], l[4];
#pragma unroll
    for (int j = 0; j < 4; j++) {
        h[j] = __float2bfloat16(f[j]);
        l[j] = __float2bfloat16(f[j] - __bfloat162float(h[j]));
    }
    __nv_bfloat162* ph = (__nv_bfloat162*)xhi;
    __nv_bfloat162* pl = (__nv_bfloat162*)xlo;
    ph[i * 2 + 0] = __nv_bfloat162(h[0], h[1]);
    ph[i * 2 + 1] = __nv_bfloat162(h[2], h[3]);
    pl[i * 2 + 0] = __nv_bfloat162(l[0], l[1]);
    pl[i * 2 + 1] = __nv_bfloat162(l[2], l[3]);
}

// W [tiles][K][N] fp32  ->  Whi/Wlo [tiles][N][K] bf16
__global__ void transpose_split_kernel(const float* __restrict__ W,
                                       bf16* __restrict__ Whi, bf16* __restrict__ Wlo,
                                       int K, int N) {
    __shared__ float t[32][33];
    const int tile = blockIdx.z;
    const float* Wt = W + (size_t)tile * K * N;
    const int n0 = blockIdx.x * 32, k0 = blockIdx.y * 32;
    for (int i = threadIdx.y; i < 32; i += 8)
        t[i][threadIdx.x] = Wt[(size_t)(k0 + i) * N + n0 + threadIdx.x];
    __syncthreads();
    const size_t base = (size_t)tile * N * K;
    for (int i = threadIdx.y; i < 32; i += 8) {
        float v = t[threadIdx.x][i];     // = W[k0+tx][n0+i]
        bf16 h = __float2bfloat16(v);
        bf16 l = __float2bfloat16(v - __bfloat162float(h));
        size_t o = base + (size_t)(n0 + i) * K + k0 + threadIdx.x;
        Whi[o] = h; Wlo[o] = l;
    }
}

// ---------------- router logits + argmax ------------------------------------
__global__ __launch_bounds__(256) void router_argmax_kernel(
    const float* __restrict__ Hr, const float* __restrict__ Wr2,
    const float* __restrict__ br2,
    float* __restrict__ out_logits, float* __restrict__ out_idx)
{
    const int token = blockIdx.x * 8 + (threadIdx.x >> 5);
    const int lane  = threadIdx.x & 31;
    const float* h  = Hr + (size_t)token * DM;

    float acc[N_TILES];
#pragma unroll
    for (int n = 0; n < N_TILES; n++) acc[n] = 0.f;
    for (int k = lane; k < DM; k += 32) {
        float hv = h[k];
        float4 w0 = *(const float4*)(Wr2 + (size_t)k * N_TILES);
        float4 w1 = *(const float4*)(Wr2 + (size_t)k * N_TILES + 4);
        acc[0] = fmaf(hv, w0.x, acc[0]); acc[1] = fmaf(hv, w0.y, acc[1]);
        acc[2] = fmaf(hv, w0.z, acc[2]); acc[3] = fmaf(hv, w0.w, acc[3]);
        acc[4] = fmaf(hv, w1.x, acc[4]); acc[5] = fmaf(hv, w1.y, acc[5]);
        acc[6] = fmaf(hv, w1.z, acc[6]); acc[7] = fmaf(hv, w1.w, acc[7]);
    }
#pragma unroll
    for (int n = 0; n < N_TILES; n++)
#pragma unroll
        for (int s = 16; s > 0; s >>= 1)
            acc[n] += __shfl_xor_sync(0xFFFFFFFFu, acc[n], s);
    if (lane == 0) {
        float best = -1e30f; int bi = 0;
#pragma unroll
        for (int n = 0; n < N_TILES; n++) {
            float l = (acc[n] + br2[n]) * 2.0f;
            if (out_logits) out_logits[(size_t)token * N_TILES + n] = l;
            if (l > best) { best = l; bi = n; }
        }
        g_tile[token] = bi;
        atomicAdd(&g_cnt[bi], 1);
        if (out_idx) out_idx[token] = (float)bi;
    }
}

__global__ void offsets_kernel() {
    if (threadIdx.x == 0) {
        int s = 0;
        for (int t = 0; t < N_TILES; t++) { g_off[t] = s; s += g_cnt[t]; }
    }
}

__global__ void scatter_kernel() {
    int i = blockIdx.x * blockDim.x + threadIdx.x;
    if (i < B_TOK) {
        int t = g_tile[i];
        int pos = g_off[t] + atomicAdd(&g_cur[t], 1);
        g_perm[pos] = i;
    }
}

// ---------------- HMMA bf16x3 GEMM (static smem, single buffer) --------------
// C[M,N] = act(A[M,K] @ W[K,N] + b). A hi/lo bf16 row-major; W transposed
// hi/lo: Wt[N][K] (K contiguous) == B col-major for mma row.col.
// bf16x3: hi*hi + hi*lo + lo*hi with fp32 accumulation.
// Block 128x128xK, 256 threads, 8 warps (2 M x 4 N), warp tile 64x32, BK=32.
// Smem rows padded to 80B (conflict-free b32 fragment loads, no swizzle).
// SINGLE static 40KB buffer. Register prefetch overlaps compute.

#define ROWB     80
#define ARR_B    (128 * ROWB)          // 10240 bytes per operand array
#define OFF_AHI  0
#define OFF_ALO  (ARR_B)
#define OFF_BHI  (2 * ARR_B)
#define OFF_BLO  (3 * ARR_B)
#define BUF_B    (4 * ARR_B)           // 40960 bytes total (static)

template<int MODE, bool ACT, bool F32OUT>
__global__ void __launch_bounds__(256) hgemm_kernel(
    const bf16* __restrict__ Ahi, const bf16* __restrict__ Alo,
    const bf16* __restrict__ Whi, const bf16* __restrict__ Wlo,
    const float* __restrict__ bg,
    float* __restrict__ Cf, bf16* __restrict__ Chi, bf16* __restrict__ Clo,
    int N, int K, int M0)
{
    const int tile = (MODE == 0) ? 0 : blockIdx.z;
    int Mvalid, moff;
    if (MODE == 0) { Mvalid = M0;          moff = 0; }
    else           { Mvalid = g_cnt[tile]; moff = g_off[tile]; }

    const int mstart = blockIdx.y * 128;
    if (mstart >= Mvalid) return;
    const int nstart = blockIdx.x * 128;

    __shared__ char smem[BUF_B];
    const int tid  = threadIdx.x;
    const int wid  = tid >> 5;
    const int lane = tid & 31;
    const int warp_m = (wid & 1) * 64;
    const int warp_n = (wid >> 1) * 32;
    const int g   = lane >> 2;          // groupID 0..7
    const int tig = lane & 3;           // thread-in-group 0..3

    // loader: one row per thread (0..127), 32B segment (tid&1 selects half)
    const int lrow = tid >> 1;
    const int kc0  = (tid & 1) * 2;     // 16B-chunk index 0 or 2
    const int ke0  = kc0 * 8;           // element offset
    const int ke1  = ke0 + 8;

    int mg = mstart + lrow; if (mg > Mvalid - 1) mg = Mvalid - 1;
    size_t aidx;
    if (MODE == 0)      aidx = (size_t)mg;
    else if (MODE == 1) aidx = (size_t)g_perm[moff + mg];
    else                aidx = (size_t)(moff + mg);
    const bf16* gah = Ahi + aidx * (size_t)K;
    const bf16* gal = Alo + aidx * (size_t)K;
    const size_t wbase = (size_t)tile * (size_t)N * (size_t)K;
    const bf16* gbh = Whi + wbase + (size_t)(nstart + lrow) * K;
    const bf16* gbl = Wlo + wbase + (size_t)(nstart + lrow) * K;

    const int nk = K >> 5;              // K / 32

    uint4 rAh0, rAh1, rAl0, rAl1, rBh0, rBh1, rBl0, rBl1;
    {
        rAh0 = *(const uint4*)(gah + ke0);  rAh1 = *(const uint4*)(gah + ke1);
        rAl0 = *(const uint4*)(gal + ke0);  rAl1 = *(const uint4*)(gal + ke1);
        rBh0 = *(const uint4*)(gbh + ke0);  rBh1 = *(const uint4*)(gbh + ke1);
        rBl0 = *(const uint4*)(gbl + ke0);  rBl1 = *(const uint4*)(gbl + ke1);
    }

    float acc[4][4][4];
#pragma unroll
    for (int i = 0; i < 4; i++)
#pragma unroll
        for (int j = 0; j < 4; j++)
#pragma unroll
            for (int c = 0; c < 4; c++) acc[i][j][c] = 0.f;

    const uint32_t stoff = (uint32_t)lrow * ROWB + (uint32_t)kc0 * 16;

    for (int kt = 0; kt < nk; kt++) {
        // stage regs -> smem (single buffer)
        *(uint4*)(smem + OFF_AHI + stoff)      = rAh0;
        *(uint4*)(smem + OFF_AHI + stoff + 16) = rAh1;
        *(uint4*)(smem + OFF_ALO + stoff)      = rAl0;
        *(uint4*)(smem + OFF_ALO + stoff + 16) = rAl1;
        *(uint4*)(smem + OFF_BHI + stoff)      = rBh0;
        *(uint4*)(smem + OFF_BHI + stoff + 16) = rBh1;
        *(uint4*)(smem + OFF_BLO + stoff)      = rBl0;
        *(uint4*)(smem + OFF_BLO + stoff + 16) = rBl1;
        __syncthreads();

        // issue next slab's global loads (overlap with compute below)
        if (kt + 1 < nk) {
            const int k0 = (kt + 1) << 5;
            rAh0 = *(const uint4*)(gah + k0 + ke0);  rAh1 = *(const uint4*)(gah + k0 + ke1);
            rAl0 = *(const uint4*)(gal + k0 + ke0);  rAl1 = *(const uint4*)(gal + k0 + ke1);
            rBh0 = *(const uint4*)(gbh + k0 + ke0);  rBh1 = *(const uint4*)(gbh + k0 + ke1);
            rBl0 = *(const uint4*)(gbl + k0 + ke0);  rBl1 = *(const uint4*)(gbl + k0 + ke1);
        }

        // compute: two k16 steps per BK=32 slab
#pragma unroll
        for (int ks = 0; ks < 2; ks++) {
            uint32_t bh[4][2], bl[4][2];
#pragma unroll
            for (int nt = 0; nt < 4; nt++) {
                const char* bp = smem + (size_t)(warp_n + nt * 8 + g) * ROWB + ks * 32 + tig * 4;
                bh[nt][0] = *(const uint32_t*)(bp + OFF_BHI);
                bh[nt][1] = *(const uint32_t*)(bp + OFF_BHI + 16);
                bl[nt][0] = *(const uint32_t*)(bp + OFF_BLO);
                bl[nt][1] = *(const uint32_t*)(bp + OFF_BLO + 16);
            }
#pragma unroll
            for (int mt = 0; mt < 4; mt++) {
                const char* ap = smem + (size_t)(warp_m + mt * 16 + g) * ROWB + ks * 32 + tig * 4;
                uint32_t ah[4], al[4];
                ah[0] = *(const uint32_t*)(ap + OFF_AHI);
                ah[1] = *(const uint32_t*)(ap + OFF_AHI + 8 * ROWB);
                ah[2] = *(const uint32_t*)(ap + OFF_AHI + 16);
                ah[3] = *(const uint32_t*)(ap + OFF_AHI + 8 * ROWB + 16);
                al[0] = *(const uint32_t*)(ap + OFF_ALO);
                al[1] = *(const uint32_t*)(ap + OFF_ALO + 8 * ROWB);
                al[2] = *(const uint32_t*)(ap + OFF_ALO + 16);
                al[3] = *(const uint32_t*)(ap + OFF_ALO + 8 * ROWB + 16);
#pragma unroll
                for (int nt = 0; nt < 4; nt++) {
                    mma16816(acc[mt][nt], ah, bh[nt]);
                    mma16816(acc[mt][nt], ah, bl[nt]);
                    mma16816(acc[mt][nt], al, bh[nt]);
                }
            }
        }
        __syncthreads();   // single buffer: next store must wait for all reads
    }

    // ---- epilogue ----
    const float* bias = bg + (size_t)tile * N;
#pragma unroll
    for (int mt = 0; mt < 4; mt++) {
#pragma unroll
        for (int half = 0; half < 2; half++) {
            const int m = mstart + warp_m + mt * 16 + g + half * 8;
            if (m >= Mvalid) continue;
            size_t orow;
            if (MODE == 0)      orow = (size_t)m;
            else if (MODE == 1) orow = (size_t)(moff + m);
            else                orow = (size_t)g_perm[moff + m];
#pragma unroll
            for (int nt = 0; nt < 4; nt++) {
                const int n = nstart + warp_n + nt * 8 + tig * 2;
                float v0 = acc[mt][nt][half * 2 + 0] + bias[n + 0];
                float v1 = acc[mt][nt][half * 2 + 1] + bias[n + 1];
                if (ACT) { v0 = gelu_exact(v0); v1 = gelu_exact(v1); }
                if (F32OUT) {
                    *(float2*)(Cf + orow * (size_t)N + n) = make_float2(v0, v1);
                } else {
                    bf16 h0 = __float2bfloat16(v0);
                    bf16 h1 = __float2bfloat16(v1);
                    bf16 l0 = __float2bfloat16(v0 - __bfloat162float(h0));
                    bf16 l1 = __float2bfloat16(v1 - __bfloat162float(h1));
                    *(__nv_bfloat162*)(Chi + orow * (size_t)N + n) = __nv_bfloat162(h0, h1);
                    *(__nv_bfloat162*)(Clo + orow * (size_t)N + n) = __nv_bfloat162(l0, l1);
                }
            }
        }
    }
}

// ---------------- launch -----------------------------------------------------
// CRITICAL: __device__ globals passed as kernel args must be resolved to their
// TRUE device addresses via cudaGetSymbolAddress. Passing the symbol directly
// from host code passes the host shadow (ATS-mapped on GB300 -> silently wrong
// memory, not a fault). This was the R3-R5 correctness bug and the R1 slowness.
#define SYMADDR(T, var, sym) \
    T* var; { void* _p; cudaGetSymbolAddress(&_p, sym); var = (T*)_p; }

extern "C" void kernel_launch(void* const* d_in, const int* in_sizes, int n_in,
                              void* d_out, int out_size)
{
    const float* x   = (const float*)d_in[0];
    const float* Wr1 = (const float*)d_in[1];
    const float* br1 = (const float*)d_in[2];
    const float* Wr2 = (const float*)d_in[3];
    const float* br2 = (const float*)d_in[4];
    const float* W1  = (const float*)d_in[5];
    const float* b1  = (const float*)d_in[6];
    const float* W2  = (const float*)d_in[7];
    const float* b2  = (const float*)d_in[8];
    const float* Wo  = (const float*)d_in[9];
    const float* bo  = (const float*)d_in[10];

    SYMADDR(bf16,  xhi,   g_xhi);   SYMADDR(bf16,  xlo,   g_xlo);
    SYMADDR(float, Hr,    g_Hr);
    SYMADDR(bf16,  H2hi,  g_H2hi);  SYMADDR(bf16,  H2lo,  g_H2lo);
    SYMADDR(bf16,  selhi, g_selhi); SYMADDR(bf16,  sello, g_sello);
    SYMADDR(bf16,  Wr1hi, g_Wr1hi); SYMADDR(bf16,  Wr1lo, g_Wr1lo);
    SYMADDR(bf16,  W1hi,  g_W1hi);  SYMADDR(bf16,  W1lo,  g_W1lo);
    SYMADDR(bf16,  W2hi,  g_W2hi);  SYMADDR(bf16,  W2lo,  g_W2lo);
    SYMADDR(bf16,  Wohi,  g_Wohi);  SYMADDR(bf16,  Wolo,  g_Wolo);

    float* out = (float*)d_out;
    float* out_main   = out;
    float* out_idx    = nullptr;
    float* out_logits = nullptr;
    const long long need_all = (long long)B_TOK * DM + B_TOK + (long long)B_TOK * N_TILES;
    if ((long long)out_size >= need_all) {
        out_idx    = out + (size_t)B_TOK * DM;
        out_logits = out + (size_t)B_TOK * DM + B_TOK;
    } else if ((long long)out_size >= (long long)B_TOK * DM + B_TOK) {
        out_idx = out + (size_t)B_TOK * DM;
    }

    // 1) counters + conversions
    zero_kernel<<<1, 32>>>();
    split_acts_kernel<<<(B_TOK * DM / 4) / 256, 256>>>(x, xhi, xlo);
    transpose_split_kernel<<<dim3(DM / 32, DM / 32, 1), dim3(32, 8)>>>(Wr1, Wr1hi, Wr1lo, DM, DM);
    transpose_split_kernel<<<dim3(DH / 32, DM / 32, N_TILES), dim3(32, 8)>>>(W1, W1hi, W1lo, DM, DH);
    transpose_split_kernel<<<dim3(DM / 32, DH / 32, N_TILES), dim3(32, 8)>>>(W2, W2hi, W2lo, DH, DM);
    transpose_split_kernel<<<dim3(DM / 32, DM / 32, 1), dim3(32, 8)>>>(Wo, Wohi, Wolo, DM, DM);

    // 2) router hidden: Hr = gelu(x @ Wr1 + br1)  (fp32 out)
    hgemm_kernel<0, true, true><<<dim3(DM / 128, B_TOK / 128), 256>>>(
        xhi, xlo, Wr1hi, Wr1lo, br1, Hr, nullptr, nullptr, DM, DM, B_TOK);

    // 3) logits + argmax + counts; 4) offsets + scatter
    router_argmax_kernel<<<B_TOK / 8, 256>>>(Hr, Wr2, br2, out_logits, out_idx);
    offsets_kernel<<<1, 1>>>();
    scatter_kernel<<<B_TOK / 256, 256>>>();

    // 5) tile MLP layer 1: gather x rows, gelu, hi/lo out (compact order)
    hgemm_kernel<1, true, false><<<dim3(DH / 128, B_TOK / 128, N_TILES), 256>>>(
        xhi, xlo, W1hi, W1lo, b1, nullptr, H2hi, H2lo, DH, DM, 0);

    // 6) tile MLP layer 2: compact in, scatter out, hi/lo
    hgemm_kernel<2, false, false><<<dim3(DM / 128, B_TOK / 128, N_TILES), 256>>>(
        H2hi, H2lo, W2hi, W2lo, b2, nullptr, selhi, sello, DM, DH, 0);

    // 7) output projection (fp32 out to d_out)
    hgemm_kernel<0, false, true><<<dim3(DM / 128, B_TOK / 128), 256>>>(
        selhi, sello, Wohi, Wolo, bo, out_main, nullptr, nullptr, DM, DM, B_TOK);
}

// round 7
// speedup vs baseline: 9.1823x; 1.1770x over previous
#include <cuda_runtime.h>
#include <cuda_bf16.h>
#include <math.h>
#include <stdint.h>

#define B_TOK   4096
#define DM      1024
#define DH      2048
#define N_TILES 8

typedef __nv_bfloat16 bf16;

// ---------------- scratch (device globals; no allocation allowed) -----------
__device__ bf16  g_xhi [B_TOK * DM];
__device__ bf16  g_xlo [B_TOK * DM];
__device__ float g_Hr  [B_TOK * DM];
__device__ bf16  g_H2hi[B_TOK * DH];
__device__ bf16  g_H2lo[B_TOK * DH];
__device__ bf16  g_selhi[B_TOK * DM];
__device__ bf16  g_sello[B_TOK * DM];
// transposed weights [tiles][N][K] (K contiguous)
__device__ bf16  g_Wr1hi[DM * DM],            g_Wr1lo[DM * DM];
__device__ bf16  g_W1hi [N_TILES * DM * DH],  g_W1lo [N_TILES * DM * DH];
__device__ bf16  g_W2hi [N_TILES * DH * DM],  g_W2lo [N_TILES * DH * DM];
__device__ bf16  g_Wohi [DM * DM],            g_Wolo [DM * DM];
__device__ int   g_tile[B_TOK];
__device__ int   g_perm[B_TOK];
__device__ int   g_cnt[N_TILES];
__device__ int   g_off[N_TILES];
__device__ int   g_cur[N_TILES];

// ---------------- helpers ----------------------------------------------------
__device__ __forceinline__ uint32_t smem_u32(const void* p) {
    uint32_t a;
    asm("{ .reg .u64 t; cvta.to.shared.u64 t, %1; cvt.u32.u64 %0, t; }"
        : "=r"(a) : "l"(p));
    return a;
}
__device__ __forceinline__ void cp_async16(uint32_t dst, const void* src) {
    asm volatile("cp.async.cg.shared.global [%0], [%1], 16;"
                 :: "r"(dst), "l"(src) : "memory");
}
__device__ __forceinline__ void cp_commit() {
    asm volatile("cp.async.commit_group;" ::: "memory");
}
__device__ __forceinline__ void cp_wait1() {
    asm volatile("cp.async.wait_group 1;" ::: "memory");
}
__device__ __forceinline__ void ldsm_x4(uint32_t* r, uint32_t addr) {
    asm volatile("ldmatrix.sync.aligned.m8n8.x4.shared.b16 {%0,%1,%2,%3}, [%4];"
                 : "=r"(r[0]), "=r"(r[1]), "=r"(r[2]), "=r"(r[3]) : "r"(addr));
}
__device__ __forceinline__ void mma16816(float* c, const uint32_t* a, const uint32_t* b) {
    asm volatile("mma.sync.aligned.m16n8k16.row.col.f32.bf16.bf16.f32 "
                 "{%0,%1,%2,%3}, {%4,%5,%6,%7}, {%8,%9}, {%0,%1,%2,%3};"
                 : "+f"(c[0]), "+f"(c[1]), "+f"(c[2]), "+f"(c[3])
                 : "r"(a[0]), "r"(a[1]), "r"(a[2]), "r"(a[3]),
                   "r"(b[0]), "r"(b[1]));
}
__device__ __forceinline__ float gelu_exact(float v) {
    return 0.5f * v * (1.0f + erff(v * 0.70710678118654752440f));
}

// ---------------- small kernels ---------------------------------------------
__global__ void zero_kernel() {
    int i = threadIdx.x;
    if (i < N_TILES) { g_cnt[i] = 0; g_cur[i] = 0; }
}

__global__ void split_acts_kernel(const float* __restrict__ src,
                                  bf16* __restrict__ xhi, bf16* __restrict__ xlo) {
    int i = blockIdx.x * blockDim.x + threadIdx.x;   // float4 index
    const float4 v = ((const float4*)src)[i];
    float f[4] = {v.x, v.y, v.z, v.w};
    bf16 h[4], l[4];
#pragma unroll
    for (int j = 0; j < 4; j++) {
        h[j] = __float2bfloat16(f[j]);
        l[j] = __float2bfloat16(f[j] - __bfloat162float(h[j]));
    }
    __nv_bfloat162* ph = (__nv_bfloat162*)xhi;
    __nv_bfloat162* pl = (__nv_bfloat162*)xlo;
    ph[i * 2 + 0] = __nv_bfloat162(h[0], h[1]);
    ph[i * 2 + 1] = __nv_bfloat162(h[2], h[3]);
    pl[i * 2 + 0] = __nv_bfloat162(l[0], l[1]);
    pl[i * 2 + 1] = __nv_bfloat162(l[2], l[3]);
}

// W [tiles][K][N] fp32  ->  Whi/Wlo [tiles][N][K] bf16.
// Tile 32(N) x 64(K); writes are bf16x2 (128B per warp on both hi and lo).
__global__ void transpose_split_kernel(const float* __restrict__ W,
                                       bf16* __restrict__ Whi, bf16* __restrict__ Wlo,
                                       int K, int N) {
    __shared__ float t[64][33];
    const int tile = blockIdx.z;
    const float* Wt = W + (size_t)tile * K * N;
    const int n0 = blockIdx.x * 32, k0 = blockIdx.y * 64;
    const int tx = threadIdx.x, ty = threadIdx.y;
    for (int i = ty; i < 64; i += 8)
        t[i][tx] = Wt[(size_t)(k0 + i) * N + n0 + tx];
    __syncthreads();
    const size_t base = (size_t)tile * N * K;
    for (int n = ty; n < 32; n += 8) {
        float v0 = t[2 * tx + 0][n];
        float v1 = t[2 * tx + 1][n];
        bf16 h0 = __float2bfloat16(v0);
        bf16 h1 = __float2bfloat16(v1);
        bf16 l0 = __float2bfloat16(v0 - __bfloat162float(h0));
        bf16 l1 = __float2bfloat16(v1 - __bfloat162float(h1));
        size_t o = base + (size_t)(n0 + n) * K + k0 + 2 * tx;
        *(__nv_bfloat162*)(Whi + o) = __nv_bfloat162(h0, h1);
        *(__nv_bfloat162*)(Wlo + o) = __nv_bfloat162(l0, l1);
    }
}

// ---------------- router logits + argmax ------------------------------------
__global__ __launch_bounds__(256) void router_argmax_kernel(
    const float* __restrict__ Hr, const float* __restrict__ Wr2,
    const float* __restrict__ br2,
    float* __restrict__ out_logits, float* __restrict__ out_idx)
{
    const int token = blockIdx.x * 8 + (threadIdx.x >> 5);
    const int lane  = threadIdx.x & 31;
    const float* h  = Hr + (size_t)token * DM;

    float acc[N_TILES];
#pragma unroll
    for (int n = 0; n < N_TILES; n++) acc[n] = 0.f;
    for (int k = lane; k < DM; k += 32) {
        float hv = h[k];
        float4 w0 = *(const float4*)(Wr2 + (size_t)k * N_TILES);
        float4 w1 = *(const float4*)(Wr2 + (size_t)k * N_TILES + 4);
        acc[0] = fmaf(hv, w0.x, acc[0]); acc[1] = fmaf(hv, w0.y, acc[1]);
        acc[2] = fmaf(hv, w0.z, acc[2]); acc[3] = fmaf(hv, w0.w, acc[3]);
        acc[4] = fmaf(hv, w1.x, acc[4]); acc[5] = fmaf(hv, w1.y, acc[5]);
        acc[6] = fmaf(hv, w1.z, acc[6]); acc[7] = fmaf(hv, w1.w, acc[7]);
    }
#pragma unroll
    for (int n = 0; n < N_TILES; n++)
#pragma unroll
        for (int s = 16; s > 0; s >>= 1)
            acc[n] += __shfl_xor_sync(0xFFFFFFFFu, acc[n], s);
    if (lane == 0) {
        float best = -1e30f; int bi = 0;
#pragma unroll
        for (int n = 0; n < N_TILES; n++) {
            float l = (acc[n] + br2[n]) * 2.0f;
            if (out_logits) out_logits[(size_t)token * N_TILES + n] = l;
            if (l > best) { best = l; bi = n; }
        }
        g_tile[token] = bi;
        atomicAdd(&g_cnt[bi], 1);
        if (out_idx) out_idx[token] = (float)bi;
    }
}

__global__ void offsets_kernel() {
    if (threadIdx.x == 0) {
        int s = 0;
        for (int t = 0; t < N_TILES; t++) { g_off[t] = s; s += g_cnt[t]; }
    }
}

__global__ void scatter_kernel() {
    int i = blockIdx.x * blockDim.x + threadIdx.x;
    if (i < B_TOK) {
        int t = g_tile[i];
        int pos = g_off[t] + atomicAdd(&g_cur[t], 1);
        g_perm[pos] = i;
    }
}

// ---------------- HMMA bf16x3 GEMM: cp.async 3-stage + ldmatrix --------------
// C[M,N] = act(A[M,K] @ W[K,N] + b). A hi/lo bf16 row-major; W transposed
// hi/lo: Wt[N][K] (K contiguous) == B col-major for mma row.col.
// bf16x3: hi*hi + hi*lo + lo*hi, fp32 accumulation.
// Block 128x128, 256 threads, 8 warps (2 M x 4 N), warp tile 64x32, BK=16.
// 3 stages x 16KB = 48KB STATIC smem. Rows 32B, no swizzle (benign 2-way
// LDSM conflict). cutlass-style: wait_group(1); barrier; issue kt+2; compute.

#define BK       16
#define ROWB     32                     // bytes per row (BK bf16)
#define ARR_B    (128 * ROWB)           // 4096 per operand array
#define SOFF_AHI 0
#define SOFF_ALO (ARR_B)
#define SOFF_BHI (2 * ARR_B)
#define SOFF_BLO (3 * ARR_B)
#define STAGE_B  (4 * ARR_B)            // 16384 per stage
#define NSTAGE   3

template<int MODE, bool ACT, bool F32OUT>
__global__ void __launch_bounds__(256) hgemm_kernel(
    const bf16* __restrict__ Ahi, const bf16* __restrict__ Alo,
    const bf16* __restrict__ Whi, const bf16* __restrict__ Wlo,
    const float* __restrict__ bg,
    float* __restrict__ Cf, bf16* __restrict__ Chi, bf16* __restrict__ Clo,
    int N, int K, int M0)
{
    const int tile = (MODE == 0) ? 0 : blockIdx.z;
    int Mvalid, moff;
    if (MODE == 0) { Mvalid = M0;          moff = 0; }
    else           { Mvalid = g_cnt[tile]; moff = g_off[tile]; }

    const int mstart = blockIdx.y * 128;
    if (mstart >= Mvalid) return;
    const int nstart = blockIdx.x * 128;

    __shared__ __align__(128) char smem[NSTAGE * STAGE_B];
    const uint32_t sb = smem_u32(smem);
    const int tid  = threadIdx.x;
    const int wid  = tid >> 5;
    const int lane = tid & 31;
    const int warp_m = (wid & 1) * 64;
    const int warp_n = (wid >> 1) * 32;
    const int g     = lane >> 2;        // groupID 0..7
    const int tig   = lane & 3;         // thread-in-group
    const int matid = lane >> 3;        // ldmatrix matrix id 0..3
    const int mrow8 = lane & 7;

    // loader: one row per thread-pair; 16B chunk = tid&1
    const int lrow = tid >> 1;
    const int kc   = tid & 1;
    const int keo  = kc * 8;            // element offset of chunk

    int mg = mstart + lrow; if (mg > Mvalid - 1) mg = Mvalid - 1;
    size_t aidx;
    if (MODE == 0)      aidx = (size_t)mg;
    else if (MODE == 1) aidx = (size_t)g_perm[moff + mg];
    else                aidx = (size_t)(moff + mg);
    const bf16* gah = Ahi + aidx * (size_t)K;
    const bf16* gal = Alo + aidx * (size_t)K;
    const size_t wbase = (size_t)tile * (size_t)N * (size_t)K;
    const bf16* gbh = Whi + wbase + (size_t)(nstart + lrow) * K;
    const bf16* gbl = Wlo + wbase + (size_t)(nstart + lrow) * K;

    const uint32_t stoff = (uint32_t)lrow * ROWB + (uint32_t)kc * 16;
    const int nk = K / BK;

    // A ldmatrix base (per mt add mt*16*ROWB): rows warp_m + (matid&1)*8 + mrow8,
    // chunk = matid>>1.
    const uint32_t a_ls = (uint32_t)(warp_m + (matid & 1) * 8 + mrow8) * ROWB
                        + (uint32_t)(matid >> 1) * 16;
    // B ldmatrix base (per np add np*16*ROWB): rows warp_n + (matid>>1)*8 + mrow8,
    // chunk = matid&1.
    const uint32_t b_ls = (uint32_t)(warp_n + (matid >> 1) * 8 + mrow8) * ROWB
                        + (uint32_t)(matid & 1) * 16;

    // prologue: stages 0 and 1
#pragma unroll
    for (int s = 0; s < 2; s++) {
        const uint32_t buf = sb + s * STAGE_B;
        const int k0 = s * BK;
        cp_async16(buf + SOFF_AHI + stoff, gah + k0 + keo);
        cp_async16(buf + SOFF_ALO + stoff, gal + k0 + keo);
        cp_async16(buf + SOFF_BHI + stoff, gbh + k0 + keo);
        cp_async16(buf + SOFF_BLO + stoff, gbl + k0 + keo);
        cp_commit();
    }

    float acc[4][4][4];
#pragma unroll
    for (int i = 0; i < 4; i++)
#pragma unroll
        for (int j = 0; j < 4; j++)
#pragma unroll
            for (int c = 0; c < 4; c++) acc[i][j][c] = 0.f;

    int sc = 0;   // stage of kt
    int sp = 2;   // stage of kt+2
    for (int kt = 0; kt < nk; kt++) {
        cp_wait1();
        __syncthreads();

        // issue stage kt+2 (buffer freed by the barrier above)
        if (kt + 2 < nk) {
            const uint32_t buf = sb + sp * STAGE_B;
            const int k0 = (kt + 2) * BK;
            cp_async16(buf + SOFF_AHI + stoff, gah + k0 + keo);
            cp_async16(buf + SOFF_ALO + stoff, gal + k0 + keo);
            cp_async16(buf + SOFF_BHI + stoff, gbh + k0 + keo);
            cp_async16(buf + SOFF_BLO + stoff, gbl + k0 + keo);
        }
        cp_commit();

        const uint32_t st = sb + sc * STAGE_B;

        // B fragments: 4 n-tiles via 2 ldmatrix.x4 each for hi/lo
        uint32_t Bh[8], Bl[8];
#pragma unroll
        for (int np = 0; np < 2; np++) {
            const uint32_t ba = st + b_ls + (uint32_t)np * 16 * ROWB;
            ldsm_x4(&Bh[np * 4], ba + SOFF_BHI);
            ldsm_x4(&Bl[np * 4], ba + SOFF_BLO);
        }
        // A per m-tile + 12 HMMA each
#pragma unroll
        for (int mt = 0; mt < 4; mt++) {
            const uint32_t aa = st + a_ls + (uint32_t)mt * 16 * ROWB;
            uint32_t Ah[4], Al[4];
            ldsm_x4(Ah, aa + SOFF_AHI);
            ldsm_x4(Al, aa + SOFF_ALO);
#pragma unroll
            for (int nt = 0; nt < 4; nt++) {
                const uint32_t* bh = &Bh[(nt >> 1) * 4 + (nt & 1) * 2];
                const uint32_t* bl = &Bl[(nt >> 1) * 4 + (nt & 1) * 2];
                mma16816(acc[mt][nt], Ah, bh);
                mma16816(acc[mt][nt], Ah, bl);
                mma16816(acc[mt][nt], Al, bh);
            }
        }

        sc = (sc == NSTAGE - 1) ? 0 : sc + 1;
        sp = (sp == NSTAGE - 1) ? 0 : sp + 1;
    }

    // ---- epilogue ----
    const float* bias = bg + (size_t)tile * N;
#pragma unroll
    for (int mt = 0; mt < 4; mt++) {
#pragma unroll
        for (int half = 0; half < 2; half++) {
            const int m = mstart + warp_m + mt * 16 + g + half * 8;
            if (m >= Mvalid) continue;
            size_t orow;
            if (MODE == 0)      orow = (size_t)m;
            else if (MODE == 1) orow = (size_t)(moff + m);
            else                orow = (size_t)g_perm[moff + m];
#pragma unroll
            for (int nt = 0; nt < 4; nt++) {
                const int n = nstart + warp_n + nt * 8 + tig * 2;
                float v0 = acc[mt][nt][half * 2 + 0] + bias[n + 0];
                float v1 = acc[mt][nt][half * 2 + 1] + bias[n + 1];
                if (ACT) { v0 = gelu_exact(v0); v1 = gelu_exact(v1); }
                if (F32OUT) {
                    *(float2*)(Cf + orow * (size_t)N + n) = make_float2(v0, v1);
                } else {
                    bf16 h0 = __float2bfloat16(v0);
                    bf16 h1 = __float2bfloat16(v1);
                    bf16 l0 = __float2bfloat16(v0 - __bfloat162float(h0));
                    bf16 l1 = __float2bfloat16(v1 - __bfloat162float(h1));
                    *(__nv_bfloat162*)(Chi + orow * (size_t)N + n) = __nv_bfloat162(h0, h1);
                    *(__nv_bfloat162*)(Clo + orow * (size_t)N + n) = __nv_bfloat162(l0, l1);
                }
            }
        }
    }
}

// ---------------- launch -----------------------------------------------------
// __device__ globals passed as kernel args MUST be resolved through
// cudaGetSymbolAddress (host shadow vs device copy under ATS on GB300).
#define SYMADDR(T, var, sym) \
    T* var; { void* _p; cudaGetSymbolAddress(&_p, sym); var = (T*)_p; }

extern "C" void kernel_launch(void* const* d_in, const int* in_sizes, int n_in,
                              void* d_out, int out_size)
{
    const float* x   = (const float*)d_in[0];
    const float* Wr1 = (const float*)d_in[1];
    const float* br1 = (const float*)d_in[2];
    const float* Wr2 = (const float*)d_in[3];
    const float* br2 = (const float*)d_in[4];
    const float* W1  = (const float*)d_in[5];
    const float* b1  = (const float*)d_in[6];
    const float* W2  = (const float*)d_in[7];
    const float* b2  = (const float*)d_in[8];
    const float* Wo  = (const float*)d_in[9];
    const float* bo  = (const float*)d_in[10];

    SYMADDR(bf16,  xhi,   g_xhi);   SYMADDR(bf16,  xlo,   g_xlo);
    SYMADDR(float, Hr,    g_Hr);
    SYMADDR(bf16,  H2hi,  g_H2hi);  SYMADDR(bf16,  H2lo,  g_H2lo);
    SYMADDR(bf16,  selhi, g_selhi); SYMADDR(bf16,  sello, g_sello);
    SYMADDR(bf16,  Wr1hi, g_Wr1hi); SYMADDR(bf16,  Wr1lo, g_Wr1lo);
    SYMADDR(bf16,  W1hi,  g_W1hi);  SYMADDR(bf16,  W1lo,  g_W1lo);
    SYMADDR(bf16,  W2hi,  g_W2hi);  SYMADDR(bf16,  W2lo,  g_W2lo);
    SYMADDR(bf16,  Wohi,  g_Wohi);  SYMADDR(bf16,  Wolo,  g_Wolo);

    float* out = (float*)d_out;
    float* out_main   = out;
    float* out_idx    = nullptr;
    float* out_logits = nullptr;
    const long long need_all = (long long)B_TOK * DM + B_TOK + (long long)B_TOK * N_TILES;
    if ((long long)out_size >= need_all) {
        out_idx    = out + (size_t)B_TOK * DM;
        out_logits = out + (size_t)B_TOK * DM + B_TOK;
    } else if ((long long)out_size >= (long long)B_TOK * DM + B_TOK) {
        out_idx = out + (size_t)B_TOK * DM;
    }

    // 1) counters + conversions
    zero_kernel<<<1, 32>>>();
    split_acts_kernel<<<(B_TOK * DM / 4) / 256, 256>>>(x, xhi, xlo);
    transpose_split_kernel<<<dim3(DM / 32, DM / 64, 1), dim3(32, 8)>>>(Wr1, Wr1hi, Wr1lo, DM, DM);
    transpose_split_kernel<<<dim3(DH / 32, DM / 64, N_TILES), dim3(32, 8)>>>(W1, W1hi, W1lo, DM, DH);
    transpose_split_kernel<<<dim3(DM / 32, DH / 64, N_TILES), dim3(32, 8)>>>(W2, W2hi, W2lo, DH, DM);
    transpose_split_kernel<<<dim3(DM / 32, DM / 64, 1), dim3(32, 8)>>>(Wo, Wohi, Wolo, DM, DM);

    // 2) router hidden: Hr = gelu(x @ Wr1 + br1)  (fp32 out)
    hgemm_kernel<0, true, true><<<dim3(DM / 128, B_TOK / 128), 256>>>(
        xhi, xlo, Wr1hi, Wr1lo, br1, Hr, nullptr, nullptr, DM, DM, B_TOK);

    // 3) logits + argmax + counts; 4) offsets + scatter
    router_argmax_kernel<<<B_TOK / 8, 256>>>(Hr, Wr2, br2, out_logits, out_idx);
    offsets_kernel<<<1, 1>>>();
    scatter_kernel<<<B_TOK / 256, 256>>>();

    // 5) tile MLP layer 1: gather x rows, gelu, hi/lo out (compact order)
    hgemm_kernel<1, true, false><<<dim3(DH / 128, B_TOK / 128, N_TILES), 256>>>(
        xhi, xlo, W1hi, W1lo, b1, nullptr, H2hi, H2lo, DH, DM, 0);

    // 6) tile MLP layer 2: compact in, scatter out, hi/lo
    hgemm_kernel<2, false, false><<<dim3(DM / 128, B_TOK / 128, N_TILES), 256>>>(
        H2hi, H2lo, W2hi, W2lo, b2, nullptr, selhi, sello, DM, DH, 0);

    // 7) output projection (fp32 out to d_out)
    hgemm_kernel<0, false, true><<<dim3(DM / 128, B_TOK / 128), 256>>>(
        selhi, sello, Wohi, Wolo, bo, out_main, nullptr, nullptr, DM, DM, B_TOK);
}

// round 8
// speedup vs baseline: 10.8071x; 1.1769x over previous
#include <cuda_runtime.h>
#include <cuda_bf16.h>
#include <math.h>
#include <stdint.h>

#define B_TOK   4096
#define DM      1024
#define DH      2048
#define N_TILES 8

typedef __nv_bfloat16 bf16;

// ---------------- scratch (device globals; no allocation allowed) -----------
__device__ bf16  g_xhi [B_TOK * DM];
__device__ bf16  g_xlo [B_TOK * DM];
__device__ float g_Hr  [B_TOK * DM];
__device__ bf16  g_H2hi[B_TOK * DH];
__device__ bf16  g_H2lo[B_TOK * DH];
__device__ bf16  g_selhi[B_TOK * DM];
__device__ bf16  g_sello[B_TOK * DM];
__device__ int   g_tile[B_TOK];
__device__ int   g_perm[B_TOK];
__device__ int   g_cnt[N_TILES];
__device__ int   g_off[N_TILES];
__device__ int   g_cur[N_TILES];

// ---------------- helpers ----------------------------------------------------
__device__ __forceinline__ uint32_t smem_u32(const void* p) {
    uint32_t a;
    asm("{ .reg .u64 t; cvta.to.shared.u64 t, %1; cvt.u32.u64 %0, t; }"
        : "=r"(a) : "l"(p));
    return a;
}
__device__ __forceinline__ void cp_async16(uint32_t dst, const void* src) {
    asm volatile("cp.async.cg.shared.global [%0], [%1], 16;"
                 :: "r"(dst), "l"(src) : "memory");
}
__device__ __forceinline__ void cp_commit() {
    asm volatile("cp.async.commit_group;" ::: "memory");
}
__device__ __forceinline__ void cp_wait1() {
    asm volatile("cp.async.wait_group 1;" ::: "memory");
}
__device__ __forceinline__ void ldsm_x4(uint32_t* r, uint32_t addr) {
    asm volatile("ldmatrix.sync.aligned.m8n8.x4.shared.b16 {%0,%1,%2,%3}, [%4];"
                 : "=r"(r[0]), "=r"(r[1]), "=r"(r[2]), "=r"(r[3]) : "r"(addr));
}
__device__ __forceinline__ void ldsm_x4_t(uint32_t* r, uint32_t addr) {
    asm volatile("ldmatrix.sync.aligned.m8n8.x4.trans.shared.b16 {%0,%1,%2,%3}, [%4];"
                 : "=r"(r[0]), "=r"(r[1]), "=r"(r[2]), "=r"(r[3]) : "r"(addr));
}
__device__ __forceinline__ void mma16816(float* c, const uint32_t* a, const uint32_t* b) {
    asm volatile("mma.sync.aligned.m16n8k16.row.col.f32.bf16.bf16.f32 "
                 "{%0,%1,%2,%3}, {%4,%5,%6,%7}, {%8,%9}, {%0,%1,%2,%3};"
                 : "+f"(c[0]), "+f"(c[1]), "+f"(c[2]), "+f"(c[3])
                 : "r"(a[0]), "r"(a[1]), "r"(a[2]), "r"(a[3]),
                   "r"(b[0]), "r"(b[1]));
}
__device__ __forceinline__ float gelu_exact(float v) {
    return 0.5f * v * (1.0f + erff(v * 0.70710678118654752440f));
}
__device__ __forceinline__ uint32_t pack_hi2(float a, float b) {
    __nv_bfloat162 p(__float2bfloat16(a), __float2bfloat16(b));
    return *(uint32_t*)&p;
}
__device__ __forceinline__ uint32_t pack_lo2(float a, float b, uint32_t hi) {
    __nv_bfloat162 h = *(__nv_bfloat162*)&hi;
    __nv_bfloat162 p(__float2bfloat16(a - __bfloat162float(h.x)),
                     __float2bfloat16(b - __bfloat162float(h.y)));
    return *(uint32_t*)&p;
}

// ---------------- small kernels ---------------------------------------------
__global__ void zero_kernel() {
    int i = threadIdx.x;
    if (i < N_TILES) { g_cnt[i] = 0; g_cur[i] = 0; }
}

__global__ void split_acts_kernel(const float* __restrict__ src,
                                  bf16* __restrict__ xhi, bf16* __restrict__ xlo) {
    int i = blockIdx.x * blockDim.x + threadIdx.x;   // float4 index
    const float4 v = ((const float4*)src)[i];
    uint32_t h0 = pack_hi2(v.x, v.y), h1 = pack_hi2(v.z, v.w);
    uint32_t l0 = pack_lo2(v.x, v.y, h0), l1 = pack_lo2(v.z, v.w, h1);
    ((uint2*)xhi)[i] = make_uint2(h0, h1);
    ((uint2*)xlo)[i] = make_uint2(l0, l1);
}

// ---------------- router logits + argmax ------------------------------------
__global__ __launch_bounds__(256) void router_argmax_kernel(
    const float* __restrict__ Hr, const float* __restrict__ Wr2,
    const float* __restrict__ br2,
    float* __restrict__ out_logits, float* __restrict__ out_idx)
{
    const int token = blockIdx.x * 8 + (threadIdx.x >> 5);
    const int lane  = threadIdx.x & 31;
    const float* h  = Hr + (size_t)token * DM;

    float acc[N_TILES];
#pragma unroll
    for (int n = 0; n < N_TILES; n++) acc[n] = 0.f;
    for (int k = lane; k < DM; k += 32) {
        float hv = h[k];
        float4 w0 = *(const float4*)(Wr2 + (size_t)k * N_TILES);
        float4 w1 = *(const float4*)(Wr2 + (size_t)k * N_TILES + 4);
        acc[0] = fmaf(hv, w0.x, acc[0]); acc[1] = fmaf(hv, w0.y, acc[1]);
        acc[2] = fmaf(hv, w0.z, acc[2]); acc[3] = fmaf(hv, w0.w, acc[3]);
        acc[4] = fmaf(hv, w1.x, acc[4]); acc[5] = fmaf(hv, w1.y, acc[5]);
        acc[6] = fmaf(hv, w1.z, acc[6]); acc[7] = fmaf(hv, w1.w, acc[7]);
    }
#pragma unroll
    for (int n = 0; n < N_TILES; n++)
#pragma unroll
        for (int s = 16; s > 0; s >>= 1)
            acc[n] += __shfl_xor_sync(0xFFFFFFFFu, acc[n], s);
    if (lane == 0) {
        float best = -1e30f; int bi = 0;
#pragma unroll
        for (int n = 0; n < N_TILES; n++) {
            float l = (acc[n] + br2[n]) * 2.0f;
            if (out_logits) out_logits[(size_t)token * N_TILES + n] = l;
            if (l > best) { best = l; bi = n; }
        }
        g_tile[token] = bi;
        atomicAdd(&g_cnt[bi], 1);
        if (out_idx) out_idx[token] = (float)bi;
    }
}

__global__ void offsets_kernel() {
    if (threadIdx.x == 0) {
        int s = 0;
        for (int t = 0; t < N_TILES; t++) { g_off[t] = s; s += g_cnt[t]; }
    }
}

__global__ void scatter_kernel() {
    int i = blockIdx.x * blockDim.x + threadIdx.x;
    if (i < B_TOK) {
        int t = g_tile[i];
        int pos = g_off[t] + atomicAdd(&g_cur[t], 1);
        g_perm[pos] = i;
    }
}

// ---------------- HMMA bf16x3 GEMM, fused fp32-weight conversion -------------
// C[M,N] = act(A[M,K] @ W[K,N] + b).
// A: hi/lo bf16 row-major, via 3-stage cp.async (proven R7 path, unchanged).
// W: fp32 [K][N] DIRECTLY from input. Loader LDGs fp32, converts to hi/lo
// bf16 in-register, STS K-major tiles [BK rows][128 n], B fragments via
// ldmatrix.x4.trans (source [k][n] transposed == col-major b0/b1 packing).
// B rows 256B with 32B-chunk XOR swizzle (2-way LDSM conflict, benign).
// bf16x3: hi*hi + hi*lo + lo*hi, fp32 accumulation.
// Block 128x128, 256 threads, 8 warps (2Mx4N), warp tile 64x32, BK=16.
// 3 stages x 16KB = 48KB static smem.

#define BK       16
#define AROWB    32                     // A row bytes (BK bf16)
#define BROWB    256                    // B row bytes (128 bf16)
#define SOFF_AHI 0
#define SOFF_ALO 4096
#define SOFF_BHI 8192
#define SOFF_BLO 12288
#define STAGE_B  16384
#define NSTAGE   3

template<int MODE, bool ACT, bool F32OUT>
__global__ void __launch_bounds__(256) hgemm_kernel(
    const bf16* __restrict__ Ahi, const bf16* __restrict__ Alo,
    const float* __restrict__ Wf,
    const float* __restrict__ bg,
    float* __restrict__ Cf, bf16* __restrict__ Chi, bf16* __restrict__ Clo,
    int N, int K, int M0)
{
    const int tile = (MODE == 0) ? 0 : blockIdx.z;
    int Mvalid, moff;
    if (MODE == 0) { Mvalid = M0;          moff = 0; }
    else           { Mvalid = g_cnt[tile]; moff = g_off[tile]; }

    const int mstart = blockIdx.y * 128;
    if (mstart >= Mvalid) return;
    const int nstart = blockIdx.x * 128;

    __shared__ __align__(128) char smem[NSTAGE * STAGE_B];
    const uint32_t sb = smem_u32(smem);
    const int tid  = threadIdx.x;
    const int wid  = tid >> 5;
    const int lane = tid & 31;
    const int warp_m = (wid & 1) * 64;
    const int warp_n = (wid >> 1) * 32;
    const int g     = lane >> 2;
    const int tig   = lane & 3;
    const int matid = lane >> 3;
    const int mrow8 = lane & 7;

    // ---- A loader (cp.async): one row per thread-pair, 16B chunk tid&1 ----
    const int lrow = tid >> 1;
    const int kc   = tid & 1;
    const int keo  = kc * 8;
    int mg = mstart + lrow; if (mg > Mvalid - 1) mg = Mvalid - 1;
    size_t aidx;
    if (MODE == 0)      aidx = (size_t)mg;
    else if (MODE == 1) aidx = (size_t)g_perm[moff + mg];
    else                aidx = (size_t)(moff + mg);
    const bf16* gah = Ahi + aidx * (size_t)K;
    const bf16* gal = Alo + aidx * (size_t)K;
    const uint32_t astoff = (uint32_t)lrow * AROWB + (uint32_t)kc * 16;

    // ---- B loader (LDG fp32 + cvt + STS): row tid>>4, 8-float seg tid&15 ----
    const int brow = tid >> 4;            // 0..15 (k within block)
    const int bseg = tid & 15;            // 8-float segment
    const float* gbf = Wf + (size_t)tile * (size_t)K * (size_t)N
                          + (size_t)nstart + (size_t)bseg * 8;
    // swizzled STS offset: chunk32 = bseg>>1, c' = chunk ^ (brow&7), sub16 = (bseg&1)*16
    const uint32_t bstoff = (uint32_t)brow * BROWB
                          + (uint32_t)(((bseg >> 1) ^ (brow & 7)) * 32)
                          + (uint32_t)((bseg & 1) * 16);

    // ---- ldmatrix addresses ----
    const uint32_t a_ls = (uint32_t)(warp_m + (matid & 1) * 8 + mrow8) * AROWB
                        + (uint32_t)(matid >> 1) * 16;
    // B trans: row = (matid&1)*8 + mrow8 (k), ncol = warp_n + np*16 + (matid>>1)*8
    const uint32_t bt_row = (uint32_t)((matid & 1) * 8 + mrow8) * BROWB
                          + (uint32_t)(matid >> 1) * 16;
    const uint32_t bt_c0 = (uint32_t)((((warp_n >> 4) + 0) ^ mrow8) * 32);
    const uint32_t bt_c1 = (uint32_t)((((warp_n >> 4) + 1) ^ mrow8) * 32);

    const int nk = K / BK;

    // B register stage (fp32, next block)
    float4 bf0, bf1;

    // ---- prologue ----
    // A stages 0,1
#pragma unroll
    for (int s = 0; s < 2; s++) {
        const uint32_t buf = sb + s * STAGE_B;
        cp_async16(buf + SOFF_AHI + astoff, gah + s * BK + keo);
        cp_async16(buf + SOFF_ALO + astoff, gal + s * BK + keo);
        cp_commit();
    }
    // B(0) -> regs -> STS stage0 ; B(1) -> regs
    {
        const float* p = gbf + (size_t)brow * N;
        bf0 = *(const float4*)(p);
        bf1 = *(const float4*)(p + 4);
        uint32_t h0 = pack_hi2(bf0.x, bf0.y), h1 = pack_hi2(bf0.z, bf0.w);
        uint32_t h2 = pack_hi2(bf1.x, bf1.y), h3 = pack_hi2(bf1.z, bf1.w);
        uint32_t l0 = pack_lo2(bf0.x, bf0.y, h0), l1 = pack_lo2(bf0.z, bf0.w, h1);
        uint32_t l2 = pack_lo2(bf1.x, bf1.y, h2), l3 = pack_lo2(bf1.z, bf1.w, h3);
        *(uint4*)(smem + SOFF_BHI + bstoff) = make_uint4(h0, h1, h2, h3);
        *(uint4*)(smem + SOFF_BLO + bstoff) = make_uint4(l0, l1, l2, l3);
        if (nk > 1) {
            const float* q = gbf + (size_t)(BK + brow) * N;
            bf0 = *(const float4*)(q);
            bf1 = *(const float4*)(q + 4);
        }
    }

    float acc[4][4][4];
#pragma unroll
    for (int i = 0; i < 4; i++)
#pragma unroll
        for (int j = 0; j < 4; j++)
#pragma unroll
            for (int c = 0; c < 4; c++) acc[i][j][c] = 0.f;

    int sc = 0;   // stage of kt
    int sp = 2;   // stage of kt+2 (A) and (kt+1)%3 = (sc+1)%3 for B
    for (int kt = 0; kt < nk; kt++) {
        cp_wait1();
        __syncthreads();

        // A(kt+2) via cp.async into stage sp
        if (kt + 2 < nk) {
            const uint32_t buf = sb + sp * STAGE_B;
            const int k0 = (kt + 2) * BK;
            cp_async16(buf + SOFF_AHI + astoff, gah + k0 + keo);
            cp_async16(buf + SOFF_ALO + astoff, gal + k0 + keo);
        }
        cp_commit();

        // B(kt+1): convert regs -> STS into stage (kt+1)%3
        if (kt + 1 < nk) {
            char* buf = smem + ((sc + 1) % NSTAGE) * STAGE_B;
            uint32_t h0 = pack_hi2(bf0.x, bf0.y), h1 = pack_hi2(bf0.z, bf0.w);
            uint32_t h2 = pack_hi2(bf1.x, bf1.y), h3 = pack_hi2(bf1.z, bf1.w);
            uint32_t l0 = pack_lo2(bf0.x, bf0.y, h0), l1 = pack_lo2(bf0.z, bf0.w, h1);
            uint32_t l2 = pack_lo2(bf1.x, bf1.y, h2), l3 = pack_lo2(bf1.z, bf1.w, h3);
            *(uint4*)(buf + SOFF_BHI + bstoff) = make_uint4(h0, h1, h2, h3);
            *(uint4*)(buf + SOFF_BLO + bstoff) = make_uint4(l0, l1, l2, l3);
        }
        // B(kt+2) -> regs
        if (kt + 2 < nk) {
            const float* q = gbf + (size_t)((kt + 2) * BK + brow) * N;
            bf0 = *(const float4*)(q);
            bf1 = *(const float4*)(q + 4);
        }

        const uint32_t st = sb + sc * STAGE_B;

        // B fragments via ldmatrix.trans: 2 x4 per hi/lo cover 4 n-tiles
        uint32_t Bh[8], Bl[8];
        ldsm_x4_t(&Bh[0], st + SOFF_BHI + bt_row + bt_c0);
        ldsm_x4_t(&Bh[4], st + SOFF_BHI + bt_row + bt_c1);
        ldsm_x4_t(&Bl[0], st + SOFF_BLO + bt_row + bt_c0);
        ldsm_x4_t(&Bl[4], st + SOFF_BLO + bt_row + bt_c1);

#pragma unroll
        for (int mt = 0; mt < 4; mt++) {
            const uint32_t aa = st + a_ls + (uint32_t)mt * 16 * AROWB;
            uint32_t Ah[4], Al[4];
            ldsm_x4(Ah, aa + SOFF_AHI);
            ldsm_x4(Al, aa + SOFF_ALO);
#pragma unroll
            for (int nt = 0; nt < 4; nt++) {
                const uint32_t* bh = &Bh[(nt >> 1) * 4 + (nt & 1) * 2];
                const uint32_t* bl = &Bl[(nt >> 1) * 4 + (nt & 1) * 2];
                mma16816(acc[mt][nt], Ah, bh);
                mma16816(acc[mt][nt], Ah, bl);
                mma16816(acc[mt][nt], Al, bh);
            }
        }

        sc = (sc == NSTAGE - 1) ? 0 : sc + 1;
        sp = (sp == NSTAGE - 1) ? 0 : sp + 1;
    }

    // ---- epilogue ----
    const float* bias = bg + (size_t)tile * N;
#pragma unroll
    for (int mt = 0; mt < 4; mt++) {
#pragma unroll
        for (int half = 0; half < 2; half++) {
            const int m = mstart + warp_m + mt * 16 + g + half * 8;
            if (m >= Mvalid) continue;
            size_t orow;
            if (MODE == 0)      orow = (size_t)m;
            else if (MODE == 1) orow = (size_t)(moff + m);
            else                orow = (size_t)g_perm[moff + m];
#pragma unroll
            for (int nt = 0; nt < 4; nt++) {
                const int n = nstart + warp_n + nt * 8 + tig * 2;
                float v0 = acc[mt][nt][half * 2 + 0] + bias[n + 0];
                float v1 = acc[mt][nt][half * 2 + 1] + bias[n + 1];
                if (ACT) { v0 = gelu_exact(v0); v1 = gelu_exact(v1); }
                if (F32OUT) {
                    *(float2*)(Cf + orow * (size_t)N + n) = make_float2(v0, v1);
                } else {
                    uint32_t h = pack_hi2(v0, v1);
                    uint32_t l = pack_lo2(v0, v1, h);
                    *(uint32_t*)(Chi + orow * (size_t)N + n) = h;
                    *(uint32_t*)(Clo + orow * (size_t)N + n) = l;
                }
            }
        }
    }
}

// ---------------- launch -----------------------------------------------------
// __device__ globals passed as kernel args MUST be resolved through
// cudaGetSymbolAddress (host shadow vs device copy under ATS on GB300).
#define SYMADDR(T, var, sym) \
    T* var; { void* _p; cudaGetSymbolAddress(&_p, sym); var = (T*)_p; }

extern "C" void kernel_launch(void* const* d_in, const int* in_sizes, int n_in,
                              void* d_out, int out_size)
{
    const float* x   = (const float*)d_in[0];
    const float* Wr1 = (const float*)d_in[1];
    const float* br1 = (const float*)d_in[2];
    const float* Wr2 = (const float*)d_in[3];
    const float* br2 = (const float*)d_in[4];
    const float* W1  = (const float*)d_in[5];
    const float* b1  = (const float*)d_in[6];
    const float* W2  = (const float*)d_in[7];
    const float* b2  = (const float*)d_in[8];
    const float* Wo  = (const float*)d_in[9];
    const float* bo  = (const float*)d_in[10];

    SYMADDR(bf16,  xhi,   g_xhi);   SYMADDR(bf16,  xlo,   g_xlo);
    SYMADDR(float, Hr,    g_Hr);
    SYMADDR(bf16,  H2hi,  g_H2hi);  SYMADDR(bf16,  H2lo,  g_H2lo);
    SYMADDR(bf16,  selhi, g_selhi); SYMADDR(bf16,  sello, g_sello);

    float* out = (float*)d_out;
    float* out_main   = out;
    float* out_idx    = nullptr;
    float* out_logits = nullptr;
    const long long need_all = (long long)B_TOK * DM + B_TOK + (long long)B_TOK * N_TILES;
    if ((long long)out_size >= need_all) {
        out_idx    = out + (size_t)B_TOK * DM;
        out_logits = out + (size_t)B_TOK * DM + B_TOK;
    } else if ((long long)out_size >= (long long)B_TOK * DM + B_TOK) {
        out_idx = out + (size_t)B_TOK * DM;
    }

    // 1) counters + activation split (weights are consumed fp32 in-GEMM now)
    zero_kernel<<<1, 32>>>();
    split_acts_kernel<<<(B_TOK * DM / 4) / 256, 256>>>(x, xhi, xlo);

    // 2) router hidden: Hr = gelu(x @ Wr1 + br1)  (fp32 out)
    hgemm_kernel<0, true, true><<<dim3(DM / 128, B_TOK / 128), 256>>>(
        xhi, xlo, Wr1, br1, Hr, nullptr, nullptr, DM, DM, B_TOK);

    // 3) logits + argmax + counts; 4) offsets + scatter
    router_argmax_kernel<<<B_TOK / 8, 256>>>(Hr, Wr2, br2, out_logits, out_idx);
    offsets_kernel<<<1, 1>>>();
    scatter_kernel<<<B_TOK / 256, 256>>>();

    // 5) tile MLP layer 1: gather x rows, gelu, hi/lo out (compact order)
    hgemm_kernel<1, true, false><<<dim3(DH / 128, B_TOK / 128, N_TILES), 256>>>(
        xhi, xlo, W1, b1, nullptr, H2hi, H2lo, DH, DM, 0);

    // 6) tile MLP layer 2: compact in, scatter out, hi/lo
    hgemm_kernel<2, false, false><<<dim3(DM / 128, B_TOK / 128, N_TILES), 256>>>(
        H2hi, H2lo, W2, b2, nullptr, selhi, sello, DM, DH, 0);

    // 7) output projection (fp32 out to d_out)
    hgemm_kernel<0, false, true><<<dim3(DM / 128, B_TOK / 128), 256>>>(
        selhi, sello, Wo, bo, out_main, nullptr, nullptr, DM, DM, B_TOK);
}